// round 6
// baseline (speedup 1.0000x reference)
#include <cuda_runtime.h>

#define T_ 512
#define K_ 8
#define D_ 8
#define CP_ 28
#define ILP 4
#define EPS_ 1e-7f

typedef unsigned long long ull;

// ---------------- precomputed params (pair-duplicated for f32x2 math) ----------------
__device__ float2 g_q2 [T_ * K_ * D_ * D_];  // (q,q) variance-scaled rotation [t][k][i][j]
__device__ float2 g_cq2[T_ * K_ * D_];       // (-sum_i c_i q[i][j]) duplicated
__device__ float2 g_nc2[T_ * K_ * D_];       // 1/sqrt(2 pi var) duplicated
__device__ float2 g_w2 [T_ * K_];            // softmax weight duplicated

__device__ __forceinline__ float ex2f(float x) {
    float r; asm("ex2.approx.ftz.f32 %0, %1;" : "=f"(r) : "f"(x)); return r;
}
__device__ __forceinline__ ull fma2(ull a, ull b, ull c) {
    ull d; asm("fma.rn.f32x2 %0, %1, %2, %3;" : "=l"(d) : "l"(a), "l"(b), "l"(c)); return d;
}
__device__ __forceinline__ ull mul2(ull a, ull b) {
    ull d; asm("mul.rn.f32x2 %0, %1, %2;" : "=l"(d) : "l"(a), "l"(b)); return d;
}
__device__ __forceinline__ ull pack2(float lo, float hi) {
    ull r; asm("mov.b64 %0, {%1, %2};" : "=l"(r) : "f"(lo), "f"(hi)); return r;
}
__device__ __forceinline__ void unpack2(ull v, float& lo, float& hi) {
    asm("mov.b64 {%0, %1}, %2;" : "=f"(lo), "=f"(hi) : "l"(v));
}

// ---------------- fused precompute: Cayley + scaling + centers + softmax ----------------
// 8 threads per (t,k) matrix; thread j owns column j of the Gauss-Jordan pair.
// Q = (I-A)(I+A)^{-1};  Q^T = (I-A)^{-1}(I+A): GJ on [N|P], N=I-A, P=I+A -> P = Q^T.
// No pivoting needed (leading minors of I-A for antisymmetric A are >= 1).
__global__ void __launch_bounds__(256) prep_kernel(const float* __restrict__ cov,
                                                   const float* __restrict__ centers,
                                                   const float* __restrict__ wlog,
                                                   const float* __restrict__ lvar) {
    const unsigned FULL = 0xffffffffu;
    int gid = blockIdx.x * 32 + (threadIdx.x >> 3);   // matrix index (t*8+k), exact 4096
    int j   = threadIdx.x & 7;                        // owned column
    const float* v = cov + gid * CP_;

    // build column j of N = I-A and P = I+A.  A[i][j] = 0.5*(UT[j][i]-UT[i][j])
    float N[D_], P[D_];
#pragma unroll
    for (int i = 0; i < D_; i++) {
        float a = 0.f;
        if (i != j) {
            int lo = i < j ? i : j, hi = i < j ? j : i;
            int m = lo * 8 + hi;
            float val = (m < CP_) ? v[m] : v[55 - m];
            a = (j > i) ? -0.5f * val : 0.5f * val;
        }
        float d = (i == j) ? 1.f : 0.f;
        N[i] = d - a;
        P[i] = d + a;
    }

    // Gauss-Jordan, columns distributed across the 8-lane group
#pragma unroll
    for (int c = 0; c < D_; c++) {
        float ncc = __shfl_sync(FULL, N[c], c, 8);
        float piv = 1.0f / ncc;
        N[c] *= piv;  P[c] *= piv;
#pragma unroll
        for (int r = 0; r < D_; r++) {
            if (r == c) continue;
            float f = __shfl_sync(FULL, N[r], c, 8);   // N[r][c], held by lane c
            N[r] = fmaf(-f, N[c], N[r]);
            P[r] = fmaf(-f, P[c], P[r]);
        }
    }
    // thread j now holds P[r] = Q^T[r][j] = Q[j][r]  (row j of Q)

    // per-dim variance scale: s[d] = sqrt(0.5*log2(e)/var)
    float lv  = fminf(fmaxf(lvar[gid * D_ + j], -3.5f), 3.5f);
    float s_own  = sqrtf(0.72134752044448169f * expf(-lv));
    float nc_own = rsqrtf(6.283185307179586f * expf(lv));

    float s_all[D_];
#pragma unroll
    for (int r = 0; r < D_; r++) s_all[r] = __shfl_sync(FULL, s_own, r, 8);

    float ce = centers[gid * D_ + j];
    float qs[D_], part[D_];
#pragma unroll
    for (int r = 0; r < D_; r++) {
        qs[r]   = P[r] * s_all[r];      // q_scaled[i=j][col=r]
        part[r] = ce * qs[r];
    }
    // reduce part[] over the 8 lanes -> cq[r] = -sum_i ce_i * q_scaled[i][r]
#pragma unroll
    for (int off = 1; off < 8; off <<= 1)
#pragma unroll
        for (int r = 0; r < D_; r++)
            part[r] += __shfl_xor_sync(FULL, part[r], off, 8);

    // stores (pair-duplicated)
    float2* qo = g_q2 + gid * (D_ * D_) + j * D_;
#pragma unroll
    for (int r = 0; r < D_; r++) qo[r] = make_float2(qs[r], qs[r]);
    g_cq2[gid * D_ + j] = make_float2(-part[j], -part[j]);
    g_nc2[gid * D_ + j] = make_float2(nc_own, nc_own);

    if (j == 0) {
        int t = gid >> 3;
        float num = expf(fminf(fmaxf(wlog[gid], -3.5f), 3.5f));
        float den = 0.f;
#pragma unroll
        for (int k = 0; k < K_; k++)
            den += expf(fminf(fmaxf(wlog[t * K_ + k], -3.5f), 3.5f));
        float w = num / den;
        g_w2[gid] = make_float2(w, w);
    }
}

// ---------------- main evaluation ----------------
// p[b,t] = sum_k w_k * prod_d (nc_d * 2^{-y_d^2} + EPS)       (log-sum-exp identity)
// ILP=4 elements per thread, packed as 2 f32x2 pairs; all main-loop math on FFMA2.
__global__ void __launch_bounds__(256) pdf_kernel(const float* __restrict__ x,
                                                  float* __restrict__ out, int B) {
    const int t   = blockIdx.y;
    const int tid = threadIdx.x;

    __shared__ ull s_q [K_ * D_ * D_];   // 4 KB (pair-duplicated)
    __shared__ ull s_cq[K_ * D_];
    __shared__ ull s_nc[K_ * D_];
    __shared__ ull s_w [K_];

    {
        const ull* gq = reinterpret_cast<const ull*>(g_q2) + (size_t)t * (K_ * D_ * D_);
        for (int i = tid; i < K_ * D_ * D_; i += 256) s_q[i] = gq[i];
        const ull* gc = reinterpret_cast<const ull*>(g_cq2) + t * (K_ * D_);
        const ull* gn = reinterpret_cast<const ull*>(g_nc2) + t * (K_ * D_);
        const ull* gw = reinterpret_cast<const ull*>(g_w2)  + t * K_;
        if (tid < 64)        s_cq[tid]       = gc[tid];
        else if (tid < 128)  s_nc[tid - 64]  = gn[tid - 64];
        else if (tid < 136)  s_w [tid - 128] = gw[tid - 128];
    }
    __syncthreads();

    const int b0 = blockIdx.x * (256 * ILP) + tid;

    // load x for 4 elements, pack into 2 pairs: pair p = elements (2p, 2p+1)
    ull xp[2][D_];
#pragma unroll
    for (int pr = 0; pr < 2; pr++) {
        float xl[D_], xh[D_];
        int bl = b0 + (2 * pr) * 256, bh = bl + 256;
#pragma unroll
        for (int d = 0; d < D_; d++) { xl[d] = 0.f; xh[d] = 0.f; }
        if (bl < B) {
            const float4* xpt = reinterpret_cast<const float4*>(x) + ((size_t)bl * T_ + t) * 2;
            float4 lo = xpt[0], hi = xpt[1];
            xl[0]=lo.x; xl[1]=lo.y; xl[2]=lo.z; xl[3]=lo.w;
            xl[4]=hi.x; xl[5]=hi.y; xl[6]=hi.z; xl[7]=hi.w;
        }
        if (bh < B) {
            const float4* xpt = reinterpret_cast<const float4*>(x) + ((size_t)bh * T_ + t) * 2;
            float4 lo = xpt[0], hi = xpt[1];
            xh[0]=lo.x; xh[1]=lo.y; xh[2]=lo.z; xh[3]=lo.w;
            xh[4]=hi.x; xh[5]=hi.y; xh[6]=hi.z; xh[7]=hi.w;
        }
#pragma unroll
        for (int d = 0; d < D_; d++) xp[pr][d] = pack2(xl[d], xh[d]);
    }

    const ull EPS2 = 0x33D6BF9533D6BF95ull;   // (1e-7f, 1e-7f)
    ull p0 = 0ull, p1 = 0ull;                 // (0.f, 0.f)

#pragma unroll 1   // body ~5KB SASS: keep rolled for L0 I-cache
    for (int k = 0; k < K_; k++) {
        const ull* qk = s_q + k * (D_ * D_);
        ull prod0, prod1;
#pragma unroll
        for (int j = 0; j < D_; j++) {
            ull y0 = s_cq[k * D_ + j];
            ull y1 = y0;
#pragma unroll
            for (int i = 0; i < D_; i++) {
                ull q = qk[i * D_ + j];
                y0 = fma2(xp[0][i], q, y0);
                y1 = fma2(xp[1][i], q, y1);
            }
            ull z0 = mul2(y0, y0);
            ull z1 = mul2(y1, y1);
            float z0l, z0h, z1l, z1h;
            unpack2(z0, z0l, z0h);
            unpack2(z1, z1l, z1h);
            ull e0 = pack2(ex2f(-z0l), ex2f(-z0h));   // neg folds into MUFU src modifier
            ull e1 = pack2(ex2f(-z1l), ex2f(-z1h));
            ull nc = s_nc[k * D_ + j];
            ull g0 = fma2(nc, e0, EPS2);
            ull g1 = fma2(nc, e1, EPS2);
            if (j == 0) { prod0 = g0; prod1 = g1; }
            else        { prod0 = mul2(prod0, g0); prod1 = mul2(prod1, g1); }
        }
        ull wk = s_w[k];
        p0 = fma2(wk, prod0, p0);
        p1 = fma2(wk, prod1, p1);
    }

    float r0, r1, r2, r3;
    unpack2(p0, r0, r1);
    unpack2(p1, r2, r3);
    int b;
    b = b0 + 0 * 256; if (b < B) out[(size_t)b * T_ + t] = r0;
    b = b0 + 1 * 256; if (b < B) out[(size_t)b * T_ + t] = r1;
    b = b0 + 2 * 256; if (b < B) out[(size_t)b * T_ + t] = r2;
    b = b0 + 3 * 256; if (b < B) out[(size_t)b * T_ + t] = r3;
}

// ---------------- launch ----------------
extern "C" void kernel_launch(void* const* d_in, const int* in_sizes, int n_in,
                              void* d_out, int out_size) {
    const float* x       = (const float*)d_in[0];
    const float* centers = (const float*)d_in[1];
    const float* wl      = (const float*)d_in[2];
    const float* lv      = (const float*)d_in[3];
    const float* cov     = (const float*)d_in[4];
    float* out = (float*)d_out;

    int B = in_sizes[0] / (T_ * D_);

    prep_kernel<<<(T_ * K_ * 8) / 256, 256>>>(cov, centers, wl, lv);

    dim3 grid((B + 256 * ILP - 1) / (256 * ILP), T_);
    pdf_kernel<<<grid, 256>>>(x, out, B);
}

// round 8
// speedup vs baseline: 1.6317x; 1.6317x over previous
#include <cuda_runtime.h>

#define T_ 512
#define K_ 8
#define D_ 8
#define CP_ 28
#define EPS_ 1e-7f

typedef unsigned long long ull;

// ---------------- precomputed params ----------------
// q transposed + pair-duplicated: g_qT[((t*K + k)*D + j)*D + i] = (v,v), v = Q[i][j]*s[j]
__device__ ull        g_qT[T_ * K_ * D_ * D_];
// combined (cq, nc) per (t,k,j): .x = dup(-sum_i c_i q_s[i][j]), .y = dup(1/sqrt(2 pi var_j))
__device__ ulonglong2 g_cn[T_ * K_ * D_];
__device__ ull        g_w2[T_ * K_];          // dup softmax weight

__device__ __forceinline__ float ex2f(float x) {
    float r; asm("ex2.approx.ftz.f32 %0, %1;" : "=f"(r) : "f"(x)); return r;
}
__device__ __forceinline__ ull fma2(ull a, ull b, ull c) {
    ull d; asm("fma.rn.f32x2 %0, %1, %2, %3;" : "=l"(d) : "l"(a), "l"(b), "l"(c)); return d;
}
__device__ __forceinline__ ull mul2(ull a, ull b) {
    ull d; asm("mul.rn.f32x2 %0, %1, %2;" : "=l"(d) : "l"(a), "l"(b)); return d;
}
__device__ __forceinline__ ull pack2(float lo, float hi) {
    ull r; asm("mov.b64 %0, {%1, %2};" : "=l"(r) : "f"(lo), "f"(hi)); return r;
}
__device__ __forceinline__ void unpack2(ull v, float& lo, float& hi) {
    asm("mov.b64 {%0, %1}, %2;" : "=f"(lo), "=f"(hi) : "l"(v));
}

// ---------------- fused precompute: Cayley + scaling + centers + softmax ----------------
// 8 threads per (t,k); thread j owns column j of the Gauss-Jordan pair [N|P],
// N=I-A, P=I+A  ->  P becomes Q^T  (Q = (I-A)(I+A)^{-1}).  No pivoting needed.
__global__ void __launch_bounds__(256) prep_kernel(const float* __restrict__ cov,
                                                   const float* __restrict__ centers,
                                                   const float* __restrict__ wlog,
                                                   const float* __restrict__ lvar) {
    const unsigned FULL = 0xffffffffu;
    int gid = blockIdx.x * 32 + (threadIdx.x >> 3);   // matrix index (t*8+k), exact 4096
    int j   = threadIdx.x & 7;                        // owned column
    const float* v = cov + gid * CP_;

    float N[D_], P[D_];
#pragma unroll
    for (int i = 0; i < D_; i++) {
        float a = 0.f;
        if (i != j) {
            int lo = i < j ? i : j, hi = i < j ? j : i;
            int m = lo * 8 + hi;
            float val = (m < CP_) ? v[m] : v[55 - m];
            a = (j > i) ? -0.5f * val : 0.5f * val;
        }
        float d = (i == j) ? 1.f : 0.f;
        N[i] = d - a;
        P[i] = d + a;
    }

#pragma unroll
    for (int c = 0; c < D_; c++) {
        float ncc = __shfl_sync(FULL, N[c], c, 8);
        float piv = 1.0f / ncc;
        N[c] *= piv;  P[c] *= piv;
#pragma unroll
        for (int r = 0; r < D_; r++) {
            if (r == c) continue;
            float f = __shfl_sync(FULL, N[r], c, 8);   // N[r][c], held by lane c
            N[r] = fmaf(-f, N[c], N[r]);
            P[r] = fmaf(-f, P[c], P[r]);
        }
    }
    // thread j holds P[r] = Q^T[r][j] = Q[j][r]

    float lv     = fminf(fmaxf(lvar[gid * D_ + j], -3.5f), 3.5f);
    float s_own  = sqrtf(0.72134752044448169f * expf(-lv));   // sqrt(0.5*log2e/var)
    float nc_own = rsqrtf(6.283185307179586f * expf(lv));

    float s_all[D_];
#pragma unroll
    for (int r = 0; r < D_; r++) s_all[r] = __shfl_sync(FULL, s_own, r, 8);

    float ce = centers[gid * D_ + j];
    float qs[D_], part[D_];
#pragma unroll
    for (int r = 0; r < D_; r++) {
        qs[r]   = P[r] * s_all[r];      // q_scaled[i=j][col=r]
        part[r] = ce * qs[r];
    }
#pragma unroll
    for (int off = 1; off < 8; off <<= 1)
#pragma unroll
        for (int r = 0; r < D_; r++)
            part[r] += __shfl_xor_sync(FULL, part[r], off, 8);

    // transposed store: g_qT[gid][col=r][i=j] = qs[r]  (inner-i contiguous)
#pragma unroll
    for (int r = 0; r < D_; r++)
        g_qT[gid * (D_ * D_) + r * D_ + j] = pack2(qs[r], qs[r]);

    g_cn[gid * D_ + j] = make_ulonglong2(pack2(-part[j], -part[j]),
                                         pack2(nc_own, nc_own));

    if (j == 0) {
        int t = gid >> 3;
        float num = expf(fminf(fmaxf(wlog[gid], -3.5f), 3.5f));
        float den = 0.f;
#pragma unroll
        for (int k = 0; k < K_; k++)
            den += expf(fminf(fmaxf(wlog[t * K_ + k], -3.5f), 3.5f));
        float w = num / den;
        g_w2[gid] = pack2(w, w);
    }
}

// ---------------- main evaluation ----------------
// p[b,t] = sum_k w_k * prod_d (nc_d * 2^{-y_d^2} + EPS)
// ILP=8 elements/thread as 4 f32x2 pairs: each shared param load feeds 4 FFMA2.
#define NTHR 128
#define BTILE (NTHR * 8)   // 1024 b per block

__global__ void __launch_bounds__(NTHR, 4) pdf_kernel(const float* __restrict__ x,
                                                      float* __restrict__ out, int B) {
    const int t   = blockIdx.y;
    const int tid = threadIdx.x;

    __shared__ ulonglong2 s_q [K_ * D_ * D_ / 2];  // [k*32 + j*4 + ii] : 4 KB
    __shared__ ulonglong2 s_cn[K_ * D_];           // 1 KB
    __shared__ ull        s_w [K_];

    {
        const ulonglong2* gq = reinterpret_cast<const ulonglong2*>(g_qT) + (size_t)t * 256;
        s_q[tid]        = gq[tid];
        s_q[tid + 128]  = gq[tid + 128];
        if (tid < 64) s_cn[tid] = g_cn[t * 64 + tid];
        else if (tid < 72) s_w[tid - 64] = g_w2[t * K_ + (tid - 64)];
    }
    __syncthreads();

    const int b0 = blockIdx.x * BTILE + tid;

    // load x for 8 elements; pair u covers b = b0 + (2u)*NTHR and b0 + (2u+1)*NTHR
    ull xp[4][D_];
#pragma unroll
    for (int u = 0; u < 4; u++) {
        float xl[D_], xh[D_];
        int bl = b0 + (2 * u) * NTHR, bh = bl + NTHR;
#pragma unroll
        for (int d = 0; d < D_; d++) { xl[d] = 0.f; xh[d] = 0.f; }
        if (bl < B) {
            const float4* xpt = reinterpret_cast<const float4*>(x) + ((size_t)bl * T_ + t) * 2;
            float4 lo = xpt[0], hi = xpt[1];
            xl[0]=lo.x; xl[1]=lo.y; xl[2]=lo.z; xl[3]=lo.w;
            xl[4]=hi.x; xl[5]=hi.y; xl[6]=hi.z; xl[7]=hi.w;
        }
        if (bh < B) {
            const float4* xpt = reinterpret_cast<const float4*>(x) + ((size_t)bh * T_ + t) * 2;
            float4 lo = xpt[0], hi = xpt[1];
            xh[0]=lo.x; xh[1]=lo.y; xh[2]=lo.z; xh[3]=lo.w;
            xh[4]=hi.x; xh[5]=hi.y; xh[6]=hi.z; xh[7]=hi.w;
        }
#pragma unroll
        for (int d = 0; d < D_; d++) xp[u][d] = pack2(xl[d], xh[d]);
    }

    const ull EPS2 = 0x33D6BF9533D6BF95ull;   // (1e-7f, 1e-7f)
    ull p[4];
#pragma unroll
    for (int u = 0; u < 4; u++) p[u] = 0ull;

#pragma unroll 1   // keep k-loop rolled (body ~9KB SASS; L1.5 I$ resident)
    for (int k = 0; k < K_; k++) {
        const ulonglong2* qk  = s_q  + k * 32;
        const ulonglong2* cnk = s_cn + k * D_;
        ull prod[4];
#pragma unroll
        for (int j = 0; j < D_; j++) {
            ulonglong2 cn = cnk[j];
            ull y[4];
#pragma unroll
            for (int u = 0; u < 4; u++) y[u] = cn.x;
#pragma unroll
            for (int ii = 0; ii < 4; ii++) {
                ulonglong2 q2 = qk[j * 4 + ii];      // q[2ii][j], q[2ii+1][j]
#pragma unroll
                for (int u = 0; u < 4; u++) y[u] = fma2(xp[u][2 * ii],     q2.x, y[u]);
#pragma unroll
                for (int u = 0; u < 4; u++) y[u] = fma2(xp[u][2 * ii + 1], q2.y, y[u]);
            }
#pragma unroll
            for (int u = 0; u < 4; u++) {
                ull z = mul2(y[u], y[u]);
                float zl, zh; unpack2(z, zl, zh);
                ull e = pack2(ex2f(-zl), ex2f(-zh));
                ull g = fma2(cn.y, e, EPS2);
                prod[u] = (j == 0) ? g : mul2(prod[u], g);
            }
        }
        ull wk = s_w[k];
#pragma unroll
        for (int u = 0; u < 4; u++) p[u] = fma2(wk, prod[u], p[u]);
    }

#pragma unroll
    for (int u = 0; u < 4; u++) {
        float rl, rh; unpack2(p[u], rl, rh);
        int bl = b0 + (2 * u) * NTHR, bh = bl + NTHR;
        if (bl < B) out[(size_t)bl * T_ + t] = rl;
        if (bh < B) out[(size_t)bh * T_ + t] = rh;
    }
}

// ---------------- launch ----------------
extern "C" void kernel_launch(void* const* d_in, const int* in_sizes, int n_in,
                              void* d_out, int out_size) {
    const float* x       = (const float*)d_in[0];
    const float* centers = (const float*)d_in[1];
    const float* wl      = (const float*)d_in[2];
    const float* lv      = (const float*)d_in[3];
    const float* cov     = (const float*)d_in[4];
    float* out = (float*)d_out;

    int B = in_sizes[0] / (T_ * D_);

    prep_kernel<<<(T_ * K_ * 8) / 256, 256>>>(cov, centers, wl, lv);

    dim3 grid((B + BTILE - 1) / BTILE, T_);
    pdf_kernel<<<grid, NTHR>>>(x, out, B);
}